// round 10
// baseline (speedup 1.0000x reference)
#include <cuda_runtime.h>
#include <cuda_fp16.h>
#include <math.h>
#include <stdint.h>

#define NF 256
#define NH 128
#define NC 10
#define NMAX 50000
#define EMAX 800000
#define SCANB 1024
#define KC 32
#define AST 40

// Scratch
__device__ __align__(16) __half g_h[(size_t)NMAX * NH];   // fp16 GEMM output
__device__ float g_agg[(size_t)NMAX * NH];
__device__ float g_deg[NMAX];
__device__ float g_dinv[NMAX];
__device__ float g_selfc[NMAX];
__device__ int   g_cnt[NMAX];
__device__ int   g_pos[NMAX];
__device__ int   g_rowoff[NMAX + 1];
__device__ int   g_csr_src[EMAX];
__device__ float g_csr_coef[EMAX];
__device__ int   g_bsum[(NMAX + SCANB - 1) / SCANB];
__device__ int   g_boff[(NMAX + SCANB - 1) / SCANB];

// ---------------- helpers ------------------------------------------------
__device__ __forceinline__ uint32_t smem_u32(const void* p) {
    uint32_t a;
    asm("{ .reg .u64 t; cvta.to.shared.u64 t, %1; cvt.u32.u64 %0, t; }"
        : "=r"(a) : "l"(p));
    return a;
}
__device__ __forceinline__ uint32_t pack_bf(float a, float b) {
    uint32_t r;
    asm("cvt.rn.bf16x2.f32 %0, %1, %2;" : "=r"(r) : "f"(b), "f"(a));
    return r;
}
__device__ __forceinline__ float bflo_f(uint32_t p) { return __uint_as_float(p << 16); }
__device__ __forceinline__ float bfhi_f(uint32_t p) { return __uint_as_float(p & 0xffff0000u); }

__device__ __forceinline__ void ldm4(uint32_t* r, uint32_t addr) {
    asm volatile("ldmatrix.sync.aligned.m8n8.x4.shared.b16 {%0,%1,%2,%3}, [%4];"
                 : "=r"(r[0]), "=r"(r[1]), "=r"(r[2]), "=r"(r[3]) : "r"(addr));
}
__device__ __forceinline__ void ldm2(uint32_t* r, uint32_t addr) {
    asm volatile("ldmatrix.sync.aligned.m8n8.x2.shared.b16 {%0,%1}, [%2];"
                 : "=r"(r[0]), "=r"(r[1]) : "r"(addr));
}
__device__ __forceinline__ void mma_bf16(float* d, const uint32_t* a, const uint32_t* b) {
    asm volatile(
        "mma.sync.aligned.m16n8k16.row.col.f32.bf16.bf16.f32 "
        "{%0,%1,%2,%3}, {%4,%5,%6,%7}, {%8,%9}, {%0,%1,%2,%3};"
        : "+f"(d[0]), "+f"(d[1]), "+f"(d[2]), "+f"(d[3])
        : "r"(a[0]), "r"(a[1]), "r"(a[2]), "r"(a[3]), "r"(b[0]), "r"(b[1]));
}

// ---------------- round-6 aggregation core (verbatim) --------------------
__device__ __forceinline__ float4 aggregate_node6(int node, int lane,
                                                  const float* __restrict__ b) {
    const __half2* h2 = reinterpret_cast<const __half2*>(g_h);
    float4 bv = reinterpret_cast<const float4*>(b)[lane];
    float sc = g_selfc[node];

    float4 acc;
    {
        __half2 a0 = h2[(size_t)node * 64 + 2 * lane];
        __half2 a1 = h2[(size_t)node * 64 + 2 * lane + 1];
        float2 f0 = __half22float2(a0);
        float2 f1 = __half22float2(a1);
        acc.x = fmaf(f0.x, sc, bv.x);
        acc.y = fmaf(f0.y, sc, bv.y);
        acc.z = fmaf(f1.x, sc, bv.z);
        acc.w = fmaf(f1.y, sc, bv.w);
    }

    int beg = g_rowoff[node];
    int end = g_rowoff[node + 1];
    int e = beg;
    for (; e + 1 < end; e += 2) {
        int s0 = __ldg(g_csr_src + e);
        int s1 = __ldg(g_csr_src + e + 1);
        float w0 = __ldg(g_csr_coef + e);
        float w1 = __ldg(g_csr_coef + e + 1);
        __half2 a0 = h2[(size_t)s0 * 64 + 2 * lane];
        __half2 a1 = h2[(size_t)s0 * 64 + 2 * lane + 1];
        __half2 c0 = h2[(size_t)s1 * 64 + 2 * lane];
        __half2 c1 = h2[(size_t)s1 * 64 + 2 * lane + 1];
        float2 f0 = __half22float2(a0);
        float2 f1 = __half22float2(a1);
        float2 g0 = __half22float2(c0);
        float2 g1 = __half22float2(c1);
        acc.x = fmaf(f0.x, w0, acc.x);
        acc.y = fmaf(f0.y, w0, acc.y);
        acc.z = fmaf(f1.x, w0, acc.z);
        acc.w = fmaf(f1.y, w0, acc.w);
        acc.x = fmaf(g0.x, w1, acc.x);
        acc.y = fmaf(g0.y, w1, acc.y);
        acc.z = fmaf(g1.x, w1, acc.z);
        acc.w = fmaf(g1.y, w1, acc.w);
    }
    if (e < end) {
        int s0 = __ldg(g_csr_src + e);
        float w0 = __ldg(g_csr_coef + e);
        __half2 a0 = h2[(size_t)s0 * 64 + 2 * lane];
        __half2 a1 = h2[(size_t)s0 * 64 + 2 * lane + 1];
        float2 f0 = __half22float2(a0);
        float2 f1 = __half22float2(a1);
        acc.x = fmaf(f0.x, w0, acc.x);
        acc.y = fmaf(f0.y, w0, acc.y);
        acc.z = fmaf(f1.x, w0, acc.z);
        acc.w = fmaf(f1.y, w0, acc.w);
    }
    return acc;
}

// ======================= tensor-core GEMM (mma.sync, bf16 split) =========
// Cm[N x 128] (fp16) = A[N x K] (fp32) @ W[K x 128]; optional relu on A read.
__global__ __launch_bounds__(256, 1) void tc_gemm(const float* __restrict__ A,
                                                  const float* __restrict__ W,
                                                  __half* __restrict__ Cm,
                                                  int N, int K, int reluA) {
    __shared__ __align__(16) uint16_t Ah[128 * AST];
    __shared__ __align__(16) uint16_t Al[128 * AST];
    __shared__ __align__(16) uint16_t Bh[128 * AST];
    __shared__ __align__(16) uint16_t Bl[128 * AST];

    int tid = threadIdx.x;
    int lane = tid & 31;
    int wid = tid >> 5;
    int wm = wid & 1;
    int wn = wid >> 1;
    int row0 = blockIdx.x * 128;

    float acc[4][4][4];
#pragma unroll
    for (int i = 0; i < 4; i++)
#pragma unroll
        for (int j = 0; j < 4; j++)
#pragma unroll
            for (int q = 0; q < 4; q++) acc[i][j][q] = 0.f;

    uint32_t aBase = smem_u32(Ah);
    uint32_t alBase = smem_u32(Al);
    uint32_t bBase = smem_u32(Bh);
    uint32_t blBase = smem_u32(Bl);

    int aLRow = lane & 15;
    int aLK = (lane >> 4) * 8;
    int bLRow = lane & 7;
    int bLK = ((lane >> 3) & 1) * 8;

    for (int kb = 0; kb < K; kb += KC) {
#pragma unroll
        for (int it = 0; it < 4; it++) {
            int idx = tid + it * 256;
            int row = idx >> 3;
            int f4 = idx & 7;
            float4 v = make_float4(0.f, 0.f, 0.f, 0.f);
            int gr = row0 + row;
            if (gr < N)
                v = *reinterpret_cast<const float4*>(A + (size_t)gr * K + kb + f4 * 4);
            if (reluA) {
                v.x = fmaxf(v.x, 0.f); v.y = fmaxf(v.y, 0.f);
                v.z = fmaxf(v.z, 0.f); v.w = fmaxf(v.w, 0.f);
            }
            uint32_t h01 = pack_bf(v.x, v.y);
            uint32_t h23 = pack_bf(v.z, v.w);
            uint32_t l01 = pack_bf(v.x - bflo_f(h01), v.y - bfhi_f(h01));
            uint32_t l23 = pack_bf(v.z - bflo_f(h23), v.w - bfhi_f(h23));
            int o = row * AST + f4 * 4;
            *reinterpret_cast<uint2*>(Ah + o) = make_uint2(h01, h23);
            *reinterpret_cast<uint2*>(Al + o) = make_uint2(l01, l23);
        }
#pragma unroll
        for (int it = 0; it < 8; it++) {
            int idx = tid + it * 256;
            int k2 = idx >> 7;
            int n = idx & 127;
            float v0 = W[(size_t)(kb + 2 * k2) * 128 + n];
            float v1 = W[(size_t)(kb + 2 * k2 + 1) * 128 + n];
            uint32_t h = pack_bf(v0, v1);
            uint32_t l = pack_bf(v0 - bflo_f(h), v1 - bfhi_f(h));
            int o = n * AST + k2 * 2;
            *reinterpret_cast<uint32_t*>(Bh + o) = h;
            *reinterpret_cast<uint32_t*>(Bl + o) = l;
        }
        __syncthreads();

#pragma unroll
        for (int ks = 0; ks < 2; ks++) {
            int k0 = ks * 16;
            uint32_t afh[4][4], afl[4][4];
#pragma unroll
            for (int mt = 0; mt < 4; mt++) {
                uint32_t off = (uint32_t)(((wm * 64 + mt * 16 + aLRow) * AST +
                                           k0 + aLK) * 2);
                ldm4(afh[mt], aBase + off);
                ldm4(afl[mt], alBase + off);
            }
            uint32_t bfh[4][2], bfl[4][2];
#pragma unroll
            for (int nt = 0; nt < 4; nt++) {
                uint32_t off = (uint32_t)(((wn * 32 + nt * 8 + bLRow) * AST +
                                           k0 + bLK) * 2);
                ldm2(bfh[nt], bBase + off);
                ldm2(bfl[nt], blBase + off);
            }
#pragma unroll
            for (int mt = 0; mt < 4; mt++)
#pragma unroll
                for (int nt = 0; nt < 4; nt++) {
                    mma_bf16(acc[mt][nt], afh[mt], bfh[nt]);
                    mma_bf16(acc[mt][nt], afh[mt], bfl[nt]);
                    mma_bf16(acc[mt][nt], afl[mt], bfh[nt]);
                }
        }
        __syncthreads();
    }

    int gid = lane >> 2;
    int tig = lane & 3;
#pragma unroll
    for (int mt = 0; mt < 4; mt++) {
        int r0 = row0 + wm * 64 + mt * 16 + gid;
        int r1 = r0 + 8;
#pragma unroll
        for (int nt = 0; nt < 4; nt++) {
            int col = wn * 32 + nt * 8 + tig * 2;
            if (r0 < N) {
                __half2 p = __floats2half2_rn(acc[mt][nt][0], acc[mt][nt][1]);
                *reinterpret_cast<__half2*>(Cm + (size_t)r0 * 128 + col) = p;
            }
            if (r1 < N) {
                __half2 p = __floats2half2_rn(acc[mt][nt][2], acc[mt][nt][3]);
                *reinterpret_cast<__half2*>(Cm + (size_t)r1 * 128 + col) = p;
            }
        }
    }
}

// ---------------- precompute ---------------------------------------------
__global__ void init_deg_kernel(int n) {
    int i = blockIdx.x * blockDim.x + threadIdx.x;
    if (i < n) { g_deg[i] = 1.0f; g_cnt[i] = 0; }
}

__global__ void accum_deg_kernel(const int* __restrict__ dst,
                                 const float* __restrict__ ew, int E) {
    int e = blockIdx.x * blockDim.x + threadIdx.x;
    if (e < E) {
        int d = dst[e];
        atomicAdd(&g_deg[d], ew[e]);
        atomicAdd(&g_cnt[d], 1);
    }
}

// scan phase1 with dinv fused (both depend only on accum_deg)
__global__ __launch_bounds__(SCANB) void scan_phase1(int n) {
    __shared__ int warpsum[32];
    int tid = threadIdx.x, lane = tid & 31, wid = tid >> 5;
    int i = blockIdx.x * SCANB + tid;

    if (i < n) {
        float d = g_deg[i];
        float r = (d > 0.0f) ? rsqrtf(d) : 0.0f;
        g_dinv[i] = r;
        g_selfc[i] = r * r;
    }

    int v = (i < n) ? g_cnt[i] : 0;
    int x = v;
#pragma unroll
    for (int off = 1; off < 32; off <<= 1) {
        int y = __shfl_up_sync(0xffffffffu, x, off);
        if (lane >= off) x += y;
    }
    if (lane == 31) warpsum[wid] = x;
    __syncthreads();
    if (wid == 0) {
        int s = warpsum[lane];
#pragma unroll
        for (int off = 1; off < 32; off <<= 1) {
            int y = __shfl_up_sync(0xffffffffu, s, off);
            if (lane >= off) s += y;
        }
        warpsum[lane] = s;
    }
    __syncthreads();
    int woff = wid ? warpsum[wid - 1] : 0;
    if (i < n) g_rowoff[i] = x + woff - v;
    if (tid == SCANB - 1) g_bsum[blockIdx.x] = x + woff;
}

__global__ void scan_phase2(int nb, int n) {
    int lane = threadIdx.x & 31;
    int wid = threadIdx.x >> 5;
    __shared__ int ws[2];
    int idx = threadIdx.x;
    int v = (idx < nb) ? g_bsum[idx] : 0;
    int x = v;
#pragma unroll
    for (int off = 1; off < 32; off <<= 1) {
        int y = __shfl_up_sync(0xffffffffu, x, off);
        if (lane >= off) x += y;
    }
    if (lane == 31) ws[wid] = x;
    __syncthreads();
    int add = (wid == 1) ? ws[0] : 0;
    if (idx < nb) g_boff[idx] = x + add - v;
    if (idx == nb - 1) g_rowoff[n] = x + add;
}

__global__ void scan_phase3(int n) {
    int i = blockIdx.x * blockDim.x + threadIdx.x;
    if (i < n) {
        int r = g_rowoff[i] + g_boff[i / SCANB];
        g_rowoff[i] = r;
        g_pos[i] = r;
    }
}

__global__ void fill_kernel(const int* __restrict__ src, const int* __restrict__ dst,
                            const float* __restrict__ ew, int E) {
    int e = blockIdx.x * blockDim.x + threadIdx.x;
    if (e < E) {
        int s = src[e], d = dst[e];
        int slot = atomicAdd(&g_pos[d], 1);
        g_csr_src[slot] = s;
        g_csr_coef[slot] = g_dinv[s] * ew[e] * g_dinv[d];
    }
}

// ---------------- gather (layers 1,2): write agg fp32 --------------------
__global__ void gather_kernel(const float* __restrict__ b, int n) {
    int t = blockIdx.x * blockDim.x + threadIdx.x;
    int node = t >> 5;
    int lane = t & 31;
    if (node >= n) return;
    float4 acc = aggregate_node6(node, lane, b);
    reinterpret_cast<float4*>(g_agg)[(size_t)node * 32 + lane] = acc;
}

// ---------------- gather (layer 3) fused with FC + softmax ---------------
__global__ void gather_fc_kernel(const float* __restrict__ b,
                                 const float* __restrict__ fw,
                                 const float* __restrict__ fb,
                                 float* __restrict__ out, int n) {
    int t = blockIdx.x * blockDim.x + threadIdx.x;
    int node = t >> 5;
    int lane = t & 31;
    if (node >= n) return;
    float4 a = aggregate_node6(node, lane, b);
    a.x = fmaxf(a.x, 0.f); a.y = fmaxf(a.y, 0.f);
    a.z = fmaxf(a.z, 0.f); a.w = fmaxf(a.w, 0.f);
    int k0 = 4 * lane;
    float acc[NC];
#pragma unroll
    for (int c = 0; c < NC; c++) {
        float s = a.x * __ldg(fw + (k0 + 0) * NC + c);
        s = fmaf(a.y, __ldg(fw + (k0 + 1) * NC + c), s);
        s = fmaf(a.z, __ldg(fw + (k0 + 2) * NC + c), s);
        s = fmaf(a.w, __ldg(fw + (k0 + 3) * NC + c), s);
        acc[c] = s;
    }
#pragma unroll
    for (int c = 0; c < NC; c++) {
#pragma unroll
        for (int off = 16; off; off >>= 1)
            acc[c] += __shfl_xor_sync(0xffffffffu, acc[c], off);
        acc[c] += fb[c];
    }
    float mx = acc[0];
#pragma unroll
    for (int c = 1; c < NC; c++) mx = fmaxf(mx, acc[c]);
    float ex[NC];
    float sum = 0.0f;
#pragma unroll
    for (int c = 0; c < NC; c++) { ex[c] = __expf(acc[c] - mx); sum += ex[c]; }
    float inv = 1.0f / sum;
    if (lane < NC) out[(size_t)node * NC + lane] = ex[lane] * inv;
}

// ---------------- launch -------------------------------------------------
extern "C" void kernel_launch(void* const* d_in, const int* in_sizes, int n_in,
                              void* d_out, int out_size) {
    const float* x  = (const float*)d_in[0];
    const int*   ei = (const int*)d_in[1];
    const float* ew = (const float*)d_in[2];
    const float* W1 = (const float*)d_in[3];
    const float* b1 = (const float*)d_in[4];
    const float* W2 = (const float*)d_in[5];
    const float* b2 = (const float*)d_in[6];
    const float* W3 = (const float*)d_in[7];
    const float* b3 = (const float*)d_in[8];
    const float* fw = (const float*)d_in[9];
    const float* fb = (const float*)d_in[10];
    float* out = (float*)d_out;

    int N = in_sizes[0] / NF;
    int E = in_sizes[2];
    const int* src = ei;
    const int* dst = ei + E;

    __half* hbuf;
    float* aggbuf;
    cudaGetSymbolAddress((void**)&hbuf, g_h);
    cudaGetSymbolAddress((void**)&aggbuf, g_agg);

    const int T = 256;
    int gN = (N + T - 1) / T;
    int gE = (E + T - 1) / T;
    int gGa = (N * 32 + T - 1) / T;
    int gG = (N + 127) / 128;
    int nb = (N + SCANB - 1) / SCANB;

    init_deg_kernel<<<gN, T>>>(N);
    accum_deg_kernel<<<gE, T>>>(dst, ew, E);
    scan_phase1<<<nb, SCANB>>>(N);
    scan_phase2<<<1, 64>>>(nb, N);
    scan_phase3<<<gN, T>>>(N);
    fill_kernel<<<gE, T>>>(src, dst, ew, E);

    tc_gemm<<<gG, T>>>(x, W1, hbuf, N, NF, 0);
    gather_kernel<<<gGa, T>>>(b1, N);
    tc_gemm<<<gG, T>>>(aggbuf, W2, hbuf, N, NH, 1);
    gather_kernel<<<gGa, T>>>(b2, N);
    tc_gemm<<<gG, T>>>(aggbuf, W3, hbuf, N, NH, 1);
    gather_fc_kernel<<<gGa, T>>>(b3, fw, fb, out, N);
}

// round 11
// speedup vs baseline: 1.1468x; 1.1468x over previous
#include <cuda_runtime.h>
#include <cuda_fp16.h>
#include <math.h>
#include <stdint.h>

#define NF 256
#define NH 128
#define NC 10
#define NMAX 50000
#define EMAX 800000
#define SCANB 1024
#define KC 32
#define AST 40

// Scratch
__device__ __align__(16) __half g_h[(size_t)NMAX * NH];   // fp16 GEMM output
__device__ float g_agg[(size_t)NMAX * NH];
__device__ float g_deg[NMAX];
__device__ float g_dinv[NMAX];
__device__ float g_selfc[NMAX];
__device__ int   g_cnt[NMAX];
__device__ int   g_pos[NMAX];
__device__ int   g_rowoff[NMAX + 1];
__device__ int   g_csr_src[EMAX];
__device__ float g_csr_coef[EMAX];
__device__ int   g_bsum[(NMAX + SCANB - 1) / SCANB];
__device__ int   g_boff[(NMAX + SCANB - 1) / SCANB];

// ---------------- helpers ------------------------------------------------
__device__ __forceinline__ uint32_t smem_u32(const void* p) {
    uint32_t a;
    asm("{ .reg .u64 t; cvta.to.shared.u64 t, %1; cvt.u32.u64 %0, t; }"
        : "=r"(a) : "l"(p));
    return a;
}
__device__ __forceinline__ uint32_t pack_bf(float a, float b) {
    uint32_t r;
    asm("cvt.rn.bf16x2.f32 %0, %1, %2;" : "=r"(r) : "f"(b), "f"(a));
    return r;
}
__device__ __forceinline__ float bflo_f(uint32_t p) { return __uint_as_float(p << 16); }
__device__ __forceinline__ float bfhi_f(uint32_t p) { return __uint_as_float(p & 0xffff0000u); }

__device__ __forceinline__ void ldm4(uint32_t* r, uint32_t addr) {
    asm volatile("ldmatrix.sync.aligned.m8n8.x4.shared.b16 {%0,%1,%2,%3}, [%4];"
                 : "=r"(r[0]), "=r"(r[1]), "=r"(r[2]), "=r"(r[3]) : "r"(addr));
}
__device__ __forceinline__ void ldm2(uint32_t* r, uint32_t addr) {
    asm volatile("ldmatrix.sync.aligned.m8n8.x2.shared.b16 {%0,%1}, [%2];"
                 : "=r"(r[0]), "=r"(r[1]) : "r"(addr));
}
__device__ __forceinline__ void mma_bf16(float* d, const uint32_t* a, const uint32_t* b) {
    asm volatile(
        "mma.sync.aligned.m16n8k16.row.col.f32.bf16.bf16.f32 "
        "{%0,%1,%2,%3}, {%4,%5,%6,%7}, {%8,%9}, {%0,%1,%2,%3};"
        : "+f"(d[0]), "+f"(d[1]), "+f"(d[2]), "+f"(d[3])
        : "r"(a[0]), "r"(a[1]), "r"(a[2]), "r"(a[3]), "r"(b[0]), "r"(b[1]));
}

// ======================= tensor-core GEMM (mma.sync, bf16 split) =========
// Cm[N x 128] (fp16) = A[N x K] (fp32) @ W[K x 128]; optional relu on A read.
__global__ __launch_bounds__(256, 1) void tc_gemm(const float* __restrict__ A,
                                                  const float* __restrict__ W,
                                                  __half* __restrict__ Cm,
                                                  int N, int K, int reluA) {
    __shared__ __align__(16) uint16_t Ah[128 * AST];
    __shared__ __align__(16) uint16_t Al[128 * AST];
    __shared__ __align__(16) uint16_t Bh[128 * AST];
    __shared__ __align__(16) uint16_t Bl[128 * AST];

    int tid = threadIdx.x;
    int lane = tid & 31;
    int wid = tid >> 5;
    int wm = wid & 1;
    int wn = wid >> 1;
    int row0 = blockIdx.x * 128;

    float acc[4][4][4];
#pragma unroll
    for (int i = 0; i < 4; i++)
#pragma unroll
        for (int j = 0; j < 4; j++)
#pragma unroll
            for (int q = 0; q < 4; q++) acc[i][j][q] = 0.f;

    uint32_t aBase = smem_u32(Ah);
    uint32_t alBase = smem_u32(Al);
    uint32_t bBase = smem_u32(Bh);
    uint32_t blBase = smem_u32(Bl);

    int aLRow = lane & 15;
    int aLK = (lane >> 4) * 8;
    int bLRow = lane & 7;
    int bLK = ((lane >> 3) & 1) * 8;

    for (int kb = 0; kb < K; kb += KC) {
#pragma unroll
        for (int it = 0; it < 4; it++) {
            int idx = tid + it * 256;
            int row = idx >> 3;
            int f4 = idx & 7;
            float4 v = make_float4(0.f, 0.f, 0.f, 0.f);
            int gr = row0 + row;
            if (gr < N)
                v = *reinterpret_cast<const float4*>(A + (size_t)gr * K + kb + f4 * 4);
            if (reluA) {
                v.x = fmaxf(v.x, 0.f); v.y = fmaxf(v.y, 0.f);
                v.z = fmaxf(v.z, 0.f); v.w = fmaxf(v.w, 0.f);
            }
            uint32_t h01 = pack_bf(v.x, v.y);
            uint32_t h23 = pack_bf(v.z, v.w);
            uint32_t l01 = pack_bf(v.x - bflo_f(h01), v.y - bfhi_f(h01));
            uint32_t l23 = pack_bf(v.z - bflo_f(h23), v.w - bfhi_f(h23));
            int o = row * AST + f4 * 4;
            *reinterpret_cast<uint2*>(Ah + o) = make_uint2(h01, h23);
            *reinterpret_cast<uint2*>(Al + o) = make_uint2(l01, l23);
        }
#pragma unroll
        for (int it = 0; it < 8; it++) {
            int idx = tid + it * 256;
            int k2 = idx >> 7;
            int n = idx & 127;
            float v0 = W[(size_t)(kb + 2 * k2) * 128 + n];
            float v1 = W[(size_t)(kb + 2 * k2 + 1) * 128 + n];
            uint32_t h = pack_bf(v0, v1);
            uint32_t l = pack_bf(v0 - bflo_f(h), v1 - bfhi_f(h));
            int o = n * AST + k2 * 2;
            *reinterpret_cast<uint32_t*>(Bh + o) = h;
            *reinterpret_cast<uint32_t*>(Bl + o) = l;
        }
        __syncthreads();

#pragma unroll
        for (int ks = 0; ks < 2; ks++) {
            int k0 = ks * 16;
            uint32_t afh[4][4], afl[4][4];
#pragma unroll
            for (int mt = 0; mt < 4; mt++) {
                uint32_t off = (uint32_t)(((wm * 64 + mt * 16 + aLRow) * AST +
                                           k0 + aLK) * 2);
                ldm4(afh[mt], aBase + off);
                ldm4(afl[mt], alBase + off);
            }
            uint32_t bfh[4][2], bfl[4][2];
#pragma unroll
            for (int nt = 0; nt < 4; nt++) {
                uint32_t off = (uint32_t)(((wn * 32 + nt * 8 + bLRow) * AST +
                                           k0 + bLK) * 2);
                ldm2(bfh[nt], bBase + off);
                ldm2(bfl[nt], blBase + off);
            }
#pragma unroll
            for (int mt = 0; mt < 4; mt++)
#pragma unroll
                for (int nt = 0; nt < 4; nt++) {
                    mma_bf16(acc[mt][nt], afh[mt], bfh[nt]);
                    mma_bf16(acc[mt][nt], afh[mt], bfl[nt]);
                    mma_bf16(acc[mt][nt], afl[mt], bfh[nt]);
                }
        }
        __syncthreads();
    }

    int gid = lane >> 2;
    int tig = lane & 3;
#pragma unroll
    for (int mt = 0; mt < 4; mt++) {
        int r0 = row0 + wm * 64 + mt * 16 + gid;
        int r1 = r0 + 8;
#pragma unroll
        for (int nt = 0; nt < 4; nt++) {
            int col = wn * 32 + nt * 8 + tig * 2;
            if (r0 < N) {
                __half2 p = __floats2half2_rn(acc[mt][nt][0], acc[mt][nt][1]);
                *reinterpret_cast<__half2*>(Cm + (size_t)r0 * 128 + col) = p;
            }
            if (r1 < N) {
                __half2 p = __floats2half2_rn(acc[mt][nt][2], acc[mt][nt][3]);
                *reinterpret_cast<__half2*>(Cm + (size_t)r1 * 128 + col) = p;
            }
        }
    }
}

// ---------------- precompute ---------------------------------------------
__global__ void init_deg_kernel(int n) {
    int i = blockIdx.x * blockDim.x + threadIdx.x;
    if (i < n) { g_deg[i] = 1.0f; g_cnt[i] = 0; }
}

__global__ void accum_deg_kernel(const int* __restrict__ dst,
                                 const float* __restrict__ ew, int E) {
    int e = blockIdx.x * blockDim.x + threadIdx.x;
    if (e < E) {
        int d = dst[e];
        atomicAdd(&g_deg[d], ew[e]);
        atomicAdd(&g_cnt[d], 1);
    }
}

// scan phase1 with dinv fused (both depend only on accum_deg)
__global__ __launch_bounds__(SCANB) void scan_phase1(int n) {
    __shared__ int warpsum[32];
    int tid = threadIdx.x, lane = tid & 31, wid = tid >> 5;
    int i = blockIdx.x * SCANB + tid;

    if (i < n) {
        float d = g_deg[i];
        float r = (d > 0.0f) ? rsqrtf(d) : 0.0f;
        g_dinv[i] = r;
        g_selfc[i] = r * r;
    }

    int v = (i < n) ? g_cnt[i] : 0;
    int x = v;
#pragma unroll
    for (int off = 1; off < 32; off <<= 1) {
        int y = __shfl_up_sync(0xffffffffu, x, off);
        if (lane >= off) x += y;
    }
    if (lane == 31) warpsum[wid] = x;
    __syncthreads();
    if (wid == 0) {
        int s = warpsum[lane];
#pragma unroll
        for (int off = 1; off < 32; off <<= 1) {
            int y = __shfl_up_sync(0xffffffffu, s, off);
            if (lane >= off) s += y;
        }
        warpsum[lane] = s;
    }
    __syncthreads();
    int woff = wid ? warpsum[wid - 1] : 0;
    if (i < n) g_rowoff[i] = x + woff - v;
    if (tid == SCANB - 1) g_bsum[blockIdx.x] = x + woff;
}

__global__ void scan_phase2(int nb, int n) {
    int lane = threadIdx.x & 31;
    int wid = threadIdx.x >> 5;
    __shared__ int ws[2];
    int idx = threadIdx.x;
    int v = (idx < nb) ? g_bsum[idx] : 0;
    int x = v;
#pragma unroll
    for (int off = 1; off < 32; off <<= 1) {
        int y = __shfl_up_sync(0xffffffffu, x, off);
        if (lane >= off) x += y;
    }
    if (lane == 31) ws[wid] = x;
    __syncthreads();
    int add = (wid == 1) ? ws[0] : 0;
    if (idx < nb) g_boff[idx] = x + add - v;
    if (idx == nb - 1) g_rowoff[n] = x + add;
}

__global__ void scan_phase3(int n) {
    int i = blockIdx.x * blockDim.x + threadIdx.x;
    if (i < n) {
        int r = g_rowoff[i] + g_boff[i / SCANB];
        g_rowoff[i] = r;
        g_pos[i] = r;
    }
}

__global__ void fill_kernel(const int* __restrict__ src, const int* __restrict__ dst,
                            const float* __restrict__ ew, int E) {
    int e = blockIdx.x * blockDim.x + threadIdx.x;
    if (e < E) {
        int s = src[e], d = dst[e];
        int slot = atomicAdd(&g_pos[d], 1);
        g_csr_src[slot] = s;
        g_csr_coef[slot] = g_dinv[s] * ew[e] * g_dinv[d];
    }
}

// ---------------- CSR gather aggregation (warp per node, fp16 h) ---------
__global__ void gather_kernel(const float* __restrict__ b, int n) {
    int t = blockIdx.x * blockDim.x + threadIdx.x;
    int node = t >> 5;
    int lane = t & 31;
    if (node >= n) return;

    const __half2* h2 = reinterpret_cast<const __half2*>(g_h);
    float4 bv = reinterpret_cast<const float4*>(b)[lane];
    float sc = g_selfc[node];

    float4 acc;
    {
        __half2 a0 = h2[(size_t)node * 64 + 2 * lane];
        __half2 a1 = h2[(size_t)node * 64 + 2 * lane + 1];
        float2 f0 = __half22float2(a0);
        float2 f1 = __half22float2(a1);
        acc.x = fmaf(f0.x, sc, bv.x);
        acc.y = fmaf(f0.y, sc, bv.y);
        acc.z = fmaf(f1.x, sc, bv.z);
        acc.w = fmaf(f1.y, sc, bv.w);
    }

    int beg = g_rowoff[node];
    int end = g_rowoff[node + 1];
    int e = beg;
    for (; e + 1 < end; e += 2) {
        int s0 = __ldg(g_csr_src + e);
        int s1 = __ldg(g_csr_src + e + 1);
        float w0 = __ldg(g_csr_coef + e);
        float w1 = __ldg(g_csr_coef + e + 1);
        __half2 a0 = h2[(size_t)s0 * 64 + 2 * lane];
        __half2 a1 = h2[(size_t)s0 * 64 + 2 * lane + 1];
        __half2 c0 = h2[(size_t)s1 * 64 + 2 * lane];
        __half2 c1 = h2[(size_t)s1 * 64 + 2 * lane + 1];
        float2 f0 = __half22float2(a0);
        float2 f1 = __half22float2(a1);
        float2 g0 = __half22float2(c0);
        float2 g1 = __half22float2(c1);
        acc.x = fmaf(f0.x, w0, acc.x);
        acc.y = fmaf(f0.y, w0, acc.y);
        acc.z = fmaf(f1.x, w0, acc.z);
        acc.w = fmaf(f1.y, w0, acc.w);
        acc.x = fmaf(g0.x, w1, acc.x);
        acc.y = fmaf(g0.y, w1, acc.y);
        acc.z = fmaf(g1.x, w1, acc.z);
        acc.w = fmaf(g1.y, w1, acc.w);
    }
    if (e < end) {
        int s0 = __ldg(g_csr_src + e);
        float w0 = __ldg(g_csr_coef + e);
        __half2 a0 = h2[(size_t)s0 * 64 + 2 * lane];
        __half2 a1 = h2[(size_t)s0 * 64 + 2 * lane + 1];
        float2 f0 = __half22float2(a0);
        float2 f1 = __half22float2(a1);
        acc.x = fmaf(f0.x, w0, acc.x);
        acc.y = fmaf(f0.y, w0, acc.y);
        acc.z = fmaf(f1.x, w0, acc.z);
        acc.w = fmaf(f1.y, w0, acc.w);
    }
    reinterpret_cast<float4*>(g_agg)[(size_t)node * 32 + lane] = acc;
}

// ---------------- FC + softmax (warp per node) ---------------------------
__global__ void fc_softmax_kernel(const float* __restrict__ fw,
                                  const float* __restrict__ fb,
                                  float* __restrict__ out, int n) {
    int warp = (blockIdx.x * blockDim.x + threadIdx.x) >> 5;
    int lane = threadIdx.x & 31;
    if (warp >= n) return;
    const float* hr = g_agg + (size_t)warp * NH;

    float acc[NC];
#pragma unroll
    for (int c = 0; c < NC; c++) acc[c] = 0.0f;
#pragma unroll
    for (int kk = 0; kk < 4; kk++) {
        int k = lane + kk * 32;
        float hv = fmaxf(hr[k], 0.0f);
#pragma unroll
        for (int c = 0; c < NC; c++) acc[c] = fmaf(hv, __ldg(fw + k * NC + c), acc[c]);
    }
#pragma unroll
    for (int c = 0; c < NC; c++) {
#pragma unroll
        for (int off = 16; off; off >>= 1)
            acc[c] += __shfl_xor_sync(0xffffffffu, acc[c], off);
        acc[c] += fb[c];
    }
    float mx = acc[0];
#pragma unroll
    for (int c = 1; c < NC; c++) mx = fmaxf(mx, acc[c]);
    float ex[NC];
    float sum = 0.0f;
#pragma unroll
    for (int c = 0; c < NC; c++) { ex[c] = __expf(acc[c] - mx); sum += ex[c]; }
    float inv = 1.0f / sum;
    if (lane < NC) out[(size_t)warp * NC + lane] = ex[lane] * inv;
}

// ---------------- launch -------------------------------------------------
extern "C" void kernel_launch(void* const* d_in, const int* in_sizes, int n_in,
                              void* d_out, int out_size) {
    const float* x  = (const float*)d_in[0];
    const int*   ei = (const int*)d_in[1];
    const float* ew = (const float*)d_in[2];
    const float* W1 = (const float*)d_in[3];
    const float* b1 = (const float*)d_in[4];
    const float* W2 = (const float*)d_in[5];
    const float* b2 = (const float*)d_in[6];
    const float* W3 = (const float*)d_in[7];
    const float* b3 = (const float*)d_in[8];
    const float* fw = (const float*)d_in[9];
    const float* fb = (const float*)d_in[10];
    float* out = (float*)d_out;

    int N = in_sizes[0] / NF;
    int E = in_sizes[2];
    const int* src = ei;
    const int* dst = ei + E;

    __half* hbuf;
    float* aggbuf;
    cudaGetSymbolAddress((void**)&hbuf, g_h);
    cudaGetSymbolAddress((void**)&aggbuf, g_agg);

    const int T = 256;
    int gN = (N + T - 1) / T;
    int gE = (E + T - 1) / T;
    int gGa = (N * 32 + T - 1) / T;
    int gG = (N + 127) / 128;
    int nb = (N + SCANB - 1) / SCANB;

    init_deg_kernel<<<gN, T>>>(N);
    accum_deg_kernel<<<gE, T>>>(dst, ew, E);
    scan_phase1<<<nb, SCANB>>>(N);
    scan_phase2<<<1, 64>>>(nb, N);
    scan_phase3<<<gN, T>>>(N);
    fill_kernel<<<gE, T>>>(src, dst, ew, E);

    tc_gemm<<<gG, T>>>(x, W1, hbuf, N, NF, 0);
    gather_kernel<<<gGa, T>>>(b1, N);
    tc_gemm<<<gG, T>>>(aggbuf, W2, hbuf, N, NH, 1);
    gather_kernel<<<gGa, T>>>(b2, N);
    tc_gemm<<<gG, T>>>(aggbuf, W3, hbuf, N, NH, 1);
    gather_kernel<<<gGa, T>>>(b3, N);
    fc_softmax_kernel<<<gGa, T>>>(fw, fb, out, N);
}

// round 12
// speedup vs baseline: 1.1562x; 1.0082x over previous
#include <cuda_runtime.h>
#include <cuda_fp16.h>
#include <math.h>
#include <stdint.h>

#define NF 256
#define NH 128
#define NC 10
#define NMAX 50000
#define EMAX 800000
#define SCANB 1024
#define KC 32
#define AST 40

// Scratch
__device__ __align__(16) __half g_h[(size_t)NMAX * NH];   // fp16 GEMM output
__device__ float g_agg[(size_t)NMAX * NH];
__device__ float g_deg[NMAX];
__device__ float g_dinv[NMAX];
__device__ float g_selfc[NMAX];
__device__ int   g_cnt[NMAX];
__device__ int   g_pos[NMAX];
__device__ int   g_rowoff[NMAX + 1];
__device__ int   g_csr_src[EMAX];
__device__ float g_csr_coef[EMAX];
__device__ int   g_bsum[(NMAX + SCANB - 1) / SCANB];

// ---------------- helpers ------------------------------------------------
__device__ __forceinline__ uint32_t smem_u32(const void* p) {
    uint32_t a;
    asm("{ .reg .u64 t; cvta.to.shared.u64 t, %1; cvt.u32.u64 %0, t; }"
        : "=r"(a) : "l"(p));
    return a;
}
__device__ __forceinline__ uint32_t pack_bf(float a, float b) {
    uint32_t r;
    asm("cvt.rn.bf16x2.f32 %0, %1, %2;" : "=r"(r) : "f"(b), "f"(a));
    return r;
}
__device__ __forceinline__ float bflo_f(uint32_t p) { return __uint_as_float(p << 16); }
__device__ __forceinline__ float bfhi_f(uint32_t p) { return __uint_as_float(p & 0xffff0000u); }

__device__ __forceinline__ void ldm4(uint32_t* r, uint32_t addr) {
    asm volatile("ldmatrix.sync.aligned.m8n8.x4.shared.b16 {%0,%1,%2,%3}, [%4];"
                 : "=r"(r[0]), "=r"(r[1]), "=r"(r[2]), "=r"(r[3]) : "r"(addr));
}
__device__ __forceinline__ void ldm2(uint32_t* r, uint32_t addr) {
    asm volatile("ldmatrix.sync.aligned.m8n8.x2.shared.b16 {%0,%1}, [%2];"
                 : "=r"(r[0]), "=r"(r[1]) : "r"(addr));
}
__device__ __forceinline__ void mma_bf16(float* d, const uint32_t* a, const uint32_t* b) {
    asm volatile(
        "mma.sync.aligned.m16n8k16.row.col.f32.bf16.bf16.f32 "
        "{%0,%1,%2,%3}, {%4,%5,%6,%7}, {%8,%9}, {%0,%1,%2,%3};"
        : "+f"(d[0]), "+f"(d[1]), "+f"(d[2]), "+f"(d[3])
        : "r"(a[0]), "r"(a[1]), "r"(a[2]), "r"(a[3]), "r"(b[0]), "r"(b[1]));
}

// ======================= tensor-core GEMM (mma.sync, bf16 split) =========
// Cm[N x 128] (fp16) = A[N x K] (fp32) @ W[K x 128]; optional relu on A read.
__global__ __launch_bounds__(256, 1) void tc_gemm(const float* __restrict__ A,
                                                  const float* __restrict__ W,
                                                  __half* __restrict__ Cm,
                                                  int N, int K, int reluA) {
    __shared__ __align__(16) uint16_t Ah[128 * AST];
    __shared__ __align__(16) uint16_t Al[128 * AST];
    __shared__ __align__(16) uint16_t Bh[128 * AST];
    __shared__ __align__(16) uint16_t Bl[128 * AST];

    int tid = threadIdx.x;
    int lane = tid & 31;
    int wid = tid >> 5;
    int wm = wid & 1;
    int wn = wid >> 1;
    int row0 = blockIdx.x * 128;

    float acc[4][4][4];
#pragma unroll
    for (int i = 0; i < 4; i++)
#pragma unroll
        for (int j = 0; j < 4; j++)
#pragma unroll
            for (int q = 0; q < 4; q++) acc[i][j][q] = 0.f;

    uint32_t aBase = smem_u32(Ah);
    uint32_t alBase = smem_u32(Al);
    uint32_t bBase = smem_u32(Bh);
    uint32_t blBase = smem_u32(Bl);

    int aLRow = lane & 15;
    int aLK = (lane >> 4) * 8;
    int bLRow = lane & 7;
    int bLK = ((lane >> 3) & 1) * 8;

    for (int kb = 0; kb < K; kb += KC) {
#pragma unroll
        for (int it = 0; it < 4; it++) {
            int idx = tid + it * 256;
            int row = idx >> 3;
            int f4 = idx & 7;
            float4 v = make_float4(0.f, 0.f, 0.f, 0.f);
            int gr = row0 + row;
            if (gr < N)
                v = *reinterpret_cast<const float4*>(A + (size_t)gr * K + kb + f4 * 4);
            if (reluA) {
                v.x = fmaxf(v.x, 0.f); v.y = fmaxf(v.y, 0.f);
                v.z = fmaxf(v.z, 0.f); v.w = fmaxf(v.w, 0.f);
            }
            uint32_t h01 = pack_bf(v.x, v.y);
            uint32_t h23 = pack_bf(v.z, v.w);
            uint32_t l01 = pack_bf(v.x - bflo_f(h01), v.y - bfhi_f(h01));
            uint32_t l23 = pack_bf(v.z - bflo_f(h23), v.w - bfhi_f(h23));
            int o = row * AST + f4 * 4;
            *reinterpret_cast<uint2*>(Ah + o) = make_uint2(h01, h23);
            *reinterpret_cast<uint2*>(Al + o) = make_uint2(l01, l23);
        }
#pragma unroll
        for (int it = 0; it < 8; it++) {
            int idx = tid + it * 256;
            int k2 = idx >> 7;
            int n = idx & 127;
            float v0 = W[(size_t)(kb + 2 * k2) * 128 + n];
            float v1 = W[(size_t)(kb + 2 * k2 + 1) * 128 + n];
            uint32_t h = pack_bf(v0, v1);
            uint32_t l = pack_bf(v0 - bflo_f(h), v1 - bfhi_f(h));
            int o = n * AST + k2 * 2;
            *reinterpret_cast<uint32_t*>(Bh + o) = h;
            *reinterpret_cast<uint32_t*>(Bl + o) = l;
        }
        __syncthreads();

#pragma unroll
        for (int ks = 0; ks < 2; ks++) {
            int k0 = ks * 16;
            uint32_t afh[4][4], afl[4][4];
#pragma unroll
            for (int mt = 0; mt < 4; mt++) {
                uint32_t off = (uint32_t)(((wm * 64 + mt * 16 + aLRow) * AST +
                                           k0 + aLK) * 2);
                ldm4(afh[mt], aBase + off);
                ldm4(afl[mt], alBase + off);
            }
            uint32_t bfh[4][2], bfl[4][2];
#pragma unroll
            for (int nt = 0; nt < 4; nt++) {
                uint32_t off = (uint32_t)(((wn * 32 + nt * 8 + bLRow) * AST +
                                           k0 + bLK) * 2);
                ldm2(bfh[nt], bBase + off);
                ldm2(bfl[nt], blBase + off);
            }
#pragma unroll
            for (int mt = 0; mt < 4; mt++)
#pragma unroll
                for (int nt = 0; nt < 4; nt++) {
                    mma_bf16(acc[mt][nt], afh[mt], bfh[nt]);
                    mma_bf16(acc[mt][nt], afh[mt], bfl[nt]);
                    mma_bf16(acc[mt][nt], afl[mt], bfh[nt]);
                }
        }
        __syncthreads();
    }

    int gid = lane >> 2;
    int tig = lane & 3;
#pragma unroll
    for (int mt = 0; mt < 4; mt++) {
        int r0 = row0 + wm * 64 + mt * 16 + gid;
        int r1 = r0 + 8;
#pragma unroll
        for (int nt = 0; nt < 4; nt++) {
            int col = wn * 32 + nt * 8 + tig * 2;
            if (r0 < N) {
                __half2 p = __floats2half2_rn(acc[mt][nt][0], acc[mt][nt][1]);
                *reinterpret_cast<__half2*>(Cm + (size_t)r0 * 128 + col) = p;
            }
            if (r1 < N) {
                __half2 p = __floats2half2_rn(acc[mt][nt][2], acc[mt][nt][3]);
                *reinterpret_cast<__half2*>(Cm + (size_t)r1 * 128 + col) = p;
            }
        }
    }
}

// ---------------- precompute ---------------------------------------------
__global__ void init_deg_kernel(int n) {
    int i = blockIdx.x * blockDim.x + threadIdx.x;
    if (i < n) { g_deg[i] = 1.0f; g_cnt[i] = 0; }
}

__global__ void accum_deg_kernel(const int* __restrict__ dst,
                                 const float* __restrict__ ew, int E) {
    int e = blockIdx.x * blockDim.x + threadIdx.x;
    if (e < E) {
        int d = dst[e];
        atomicAdd(&g_deg[d], ew[e]);
        atomicAdd(&g_cnt[d], 1);
    }
}

// scan phase1 with dinv fused (both depend only on accum_deg)
__global__ __launch_bounds__(SCANB) void scan_phase1(int n) {
    __shared__ int warpsum[32];
    int tid = threadIdx.x, lane = tid & 31, wid = tid >> 5;
    int i = blockIdx.x * SCANB + tid;

    if (i < n) {
        float d = g_deg[i];
        float r = (d > 0.0f) ? rsqrtf(d) : 0.0f;
        g_dinv[i] = r;
        g_selfc[i] = r * r;
    }

    int v = (i < n) ? g_cnt[i] : 0;
    int x = v;
#pragma unroll
    for (int off = 1; off < 32; off <<= 1) {
        int y = __shfl_up_sync(0xffffffffu, x, off);
        if (lane >= off) x += y;
    }
    if (lane == 31) warpsum[wid] = x;
    __syncthreads();
    if (wid == 0) {
        int s = warpsum[lane];
#pragma unroll
        for (int off = 1; off < 32; off <<= 1) {
            int y = __shfl_up_sync(0xffffffffu, s, off);
            if (lane >= off) s += y;
        }
        warpsum[lane] = s;
    }
    __syncthreads();
    int woff = wid ? warpsum[wid - 1] : 0;
    if (i < n) g_rowoff[i] = x + woff - v;
    if (tid == SCANB - 1) g_bsum[blockIdx.x] = x + woff;
}

// scan phase2+3 merged: each block redundantly scans <=64 block sums in smem,
// then applies offsets and inits g_pos.
__global__ void scan_phase23(int nb, int n) {
    __shared__ int boff_s[64];
    __shared__ int ws2[2];
    int tid = threadIdx.x;
    int lane = tid & 31;
    int w = tid >> 5;

    int v = 0, x = 0;
    if (tid < 64) {
        v = (tid < nb) ? g_bsum[tid] : 0;
        x = v;
#pragma unroll
        for (int off = 1; off < 32; off <<= 1) {
            int y = __shfl_up_sync(0xffffffffu, x, off);
            if (lane >= off) x += y;
        }
        if (lane == 31) ws2[w] = x;
    }
    __syncthreads();
    if (tid < 64) {
        int add = (w == 1) ? ws2[0] : 0;
        boff_s[tid] = x + add - v;   // exclusive prefix
        if (blockIdx.x == 0 && tid == nb - 1) g_rowoff[n] = x + add;
    }
    __syncthreads();

    int i = blockIdx.x * blockDim.x + tid;
    if (i < n) {
        int r = g_rowoff[i] + boff_s[i / SCANB];
        g_rowoff[i] = r;
        g_pos[i] = r;
    }
}

__global__ void fill_kernel(const int* __restrict__ src, const int* __restrict__ dst,
                            const float* __restrict__ ew, int E) {
    int e = blockIdx.x * blockDim.x + threadIdx.x;
    if (e < E) {
        int s = src[e], d = dst[e];
        int slot = atomicAdd(&g_pos[d], 1);
        g_csr_src[slot] = s;
        g_csr_coef[slot] = g_dinv[s] * ew[e] * g_dinv[d];
    }
}

// ---------------- CSR gather aggregation (warp per node, fp16 h) ---------
__global__ void gather_kernel(const float* __restrict__ b, int n) {
    int t = blockIdx.x * blockDim.x + threadIdx.x;
    int node = t >> 5;
    int lane = t & 31;
    if (node >= n) return;

    const __half2* h2 = reinterpret_cast<const __half2*>(g_h);
    float4 bv = reinterpret_cast<const float4*>(b)[lane];
    float sc = g_selfc[node];

    float4 acc;
    {
        __half2 a0 = h2[(size_t)node * 64 + 2 * lane];
        __half2 a1 = h2[(size_t)node * 64 + 2 * lane + 1];
        float2 f0 = __half22float2(a0);
        float2 f1 = __half22float2(a1);
        acc.x = fmaf(f0.x, sc, bv.x);
        acc.y = fmaf(f0.y, sc, bv.y);
        acc.z = fmaf(f1.x, sc, bv.z);
        acc.w = fmaf(f1.y, sc, bv.w);
    }

    int beg = g_rowoff[node];
    int end = g_rowoff[node + 1];
    int e = beg;
    for (; e + 3 < end; e += 4) {
        int s0 = __ldg(g_csr_src + e);
        int s1 = __ldg(g_csr_src + e + 1);
        int s2 = __ldg(g_csr_src + e + 2);
        int s3 = __ldg(g_csr_src + e + 3);
        float w0 = __ldg(g_csr_coef + e);
        float w1 = __ldg(g_csr_coef + e + 1);
        float w2 = __ldg(g_csr_coef + e + 2);
        float w3 = __ldg(g_csr_coef + e + 3);
        __half2 a0 = h2[(size_t)s0 * 64 + 2 * lane];
        __half2 a1 = h2[(size_t)s0 * 64 + 2 * lane + 1];
        __half2 c0 = h2[(size_t)s1 * 64 + 2 * lane];
        __half2 c1 = h2[(size_t)s1 * 64 + 2 * lane + 1];
        __half2 d0 = h2[(size_t)s2 * 64 + 2 * lane];
        __half2 d1 = h2[(size_t)s2 * 64 + 2 * lane + 1];
        __half2 e0 = h2[(size_t)s3 * 64 + 2 * lane];
        __half2 e1 = h2[(size_t)s3 * 64 + 2 * lane + 1];
        float2 f0 = __half22float2(a0);
        float2 f1 = __half22float2(a1);
        float2 g0 = __half22float2(c0);
        float2 g1 = __half22float2(c1);
        float2 h0 = __half22float2(d0);
        float2 h1 = __half22float2(d1);
        float2 i0 = __half22float2(e0);
        float2 i1 = __half22float2(e1);
        acc.x = fmaf(f0.x, w0, acc.x);
        acc.y = fmaf(f0.y, w0, acc.y);
        acc.z = fmaf(f1.x, w0, acc.z);
        acc.w = fmaf(f1.y, w0, acc.w);
        acc.x = fmaf(g0.x, w1, acc.x);
        acc.y = fmaf(g0.y, w1, acc.y);
        acc.z = fmaf(g1.x, w1, acc.z);
        acc.w = fmaf(g1.y, w1, acc.w);
        acc.x = fmaf(h0.x, w2, acc.x);
        acc.y = fmaf(h0.y, w2, acc.y);
        acc.z = fmaf(h1.x, w2, acc.z);
        acc.w = fmaf(h1.y, w2, acc.w);
        acc.x = fmaf(i0.x, w3, acc.x);
        acc.y = fmaf(i0.y, w3, acc.y);
        acc.z = fmaf(i1.x, w3, acc.z);
        acc.w = fmaf(i1.y, w3, acc.w);
    }
    for (; e < end; e++) {
        int s0 = __ldg(g_csr_src + e);
        float w0 = __ldg(g_csr_coef + e);
        __half2 a0 = h2[(size_t)s0 * 64 + 2 * lane];
        __half2 a1 = h2[(size_t)s0 * 64 + 2 * lane + 1];
        float2 f0 = __half22float2(a0);
        float2 f1 = __half22float2(a1);
        acc.x = fmaf(f0.x, w0, acc.x);
        acc.y = fmaf(f0.y, w0, acc.y);
        acc.z = fmaf(f1.x, w0, acc.z);
        acc.w = fmaf(f1.y, w0, acc.w);
    }
    reinterpret_cast<float4*>(g_agg)[(size_t)node * 32 + lane] = acc;
}

// ---------------- FC + softmax (warp per node) ---------------------------
__global__ void fc_softmax_kernel(const float* __restrict__ fw,
                                  const float* __restrict__ fb,
                                  float* __restrict__ out, int n) {
    int warp = (blockIdx.x * blockDim.x + threadIdx.x) >> 5;
    int lane = threadIdx.x & 31;
    if (warp >= n) return;
    const float* hr = g_agg + (size_t)warp * NH;

    float acc[NC];
#pragma unroll
    for (int c = 0; c < NC; c++) acc[c] = 0.0f;
#pragma unroll
    for (int kk = 0; kk < 4; kk++) {
        int k = lane + kk * 32;
        float hv = fmaxf(hr[k], 0.0f);
#pragma unroll
        for (int c = 0; c < NC; c++) acc[c] = fmaf(hv, __ldg(fw + k * NC + c), acc[c]);
    }
#pragma unroll
    for (int c = 0; c < NC; c++) {
#pragma unroll
        for (int off = 16; off; off >>= 1)
            acc[c] += __shfl_xor_sync(0xffffffffu, acc[c], off);
        acc[c] += fb[c];
    }
    float mx = acc[0];
#pragma unroll
    for (int c = 1; c < NC; c++) mx = fmaxf(mx, acc[c]);
    float ex[NC];
    float sum = 0.0f;
#pragma unroll
    for (int c = 0; c < NC; c++) { ex[c] = __expf(acc[c] - mx); sum += ex[c]; }
    float inv = 1.0f / sum;
    if (lane < NC) out[(size_t)warp * NC + lane] = ex[lane] * inv;
}

// ---------------- launch -------------------------------------------------
extern "C" void kernel_launch(void* const* d_in, const int* in_sizes, int n_in,
                              void* d_out, int out_size) {
    const float* x  = (const float*)d_in[0];
    const int*   ei = (const int*)d_in[1];
    const float* ew = (const float*)d_in[2];
    const float* W1 = (const float*)d_in[3];
    const float* b1 = (const float*)d_in[4];
    const float* W2 = (const float*)d_in[5];
    const float* b2 = (const float*)d_in[6];
    const float* W3 = (const float*)d_in[7];
    const float* b3 = (const float*)d_in[8];
    const float* fw = (const float*)d_in[9];
    const float* fb = (const float*)d_in[10];
    float* out = (float*)d_out;

    int N = in_sizes[0] / NF;
    int E = in_sizes[2];
    const int* src = ei;
    const int* dst = ei + E;

    __half* hbuf;
    float* aggbuf;
    cudaGetSymbolAddress((void**)&hbuf, g_h);
    cudaGetSymbolAddress((void**)&aggbuf, g_agg);

    const int T = 256;
    int gN = (N + T - 1) / T;
    int gE = (E + T - 1) / T;
    int gGa = (N * 32 + T - 1) / T;
    int gG = (N + 127) / 128;
    int nb = (N + SCANB - 1) / SCANB;

    init_deg_kernel<<<gN, T>>>(N);
    accum_deg_kernel<<<gE, T>>>(dst, ew, E);
    scan_phase1<<<nb, SCANB>>>(N);
    scan_phase23<<<gN, T>>>(nb, N);
    fill_kernel<<<gE, T>>>(src, dst, ew, E);

    tc_gemm<<<gG, T>>>(x, W1, hbuf, N, NF, 0);
    gather_kernel<<<gGa, T>>>(b1, N);
    tc_gemm<<<gG, T>>>(aggbuf, W2, hbuf, N, NH, 1);
    gather_kernel<<<gGa, T>>>(b2, N);
    tc_gemm<<<gG, T>>>(aggbuf, W3, hbuf, N, NH, 1);
    gather_kernel<<<gGa, T>>>(b3, N);
    fc_softmax_kernel<<<gGa, T>>>(fw, fb, out, N);
}

// round 13
// speedup vs baseline: 1.2299x; 1.0637x over previous
#include <cuda_runtime.h>
#include <cuda_fp16.h>
#include <math.h>
#include <stdint.h>

#define NF 256
#define NH 128
#define NC 10
#define NMAX 50000
#define EMAX 800000
#define SCANB 1024
#define KC 16
#define AST 24

// Scratch
__device__ __align__(16) __half g_h[(size_t)NMAX * NH];   // fp16 GEMM output
__device__ float g_agg[(size_t)NMAX * NH];
__device__ float g_deg[NMAX];
__device__ float g_dinv[NMAX];
__device__ float g_selfc[NMAX];
__device__ int   g_cnt[NMAX];
__device__ int   g_pos[NMAX];
__device__ int   g_rowoff[NMAX + 1];
__device__ int   g_csr_src[EMAX];
__device__ float g_csr_coef[EMAX];
__device__ int   g_bsum[(NMAX + SCANB - 1) / SCANB];

// ---------------- helpers ------------------------------------------------
__device__ __forceinline__ uint32_t smem_u32(const void* p) {
    uint32_t a;
    asm("{ .reg .u64 t; cvta.to.shared.u64 t, %1; cvt.u32.u64 %0, t; }"
        : "=r"(a) : "l"(p));
    return a;
}
__device__ __forceinline__ uint32_t pack_bf(float a, float b) {
    uint32_t r;
    asm("cvt.rn.bf16x2.f32 %0, %1, %2;" : "=r"(r) : "f"(b), "f"(a));
    return r;
}
__device__ __forceinline__ float bflo_f(uint32_t p) { return __uint_as_float(p << 16); }
__device__ __forceinline__ float bfhi_f(uint32_t p) { return __uint_as_float(p & 0xffff0000u); }

__device__ __forceinline__ void ldm4(uint32_t* r, uint32_t addr) {
    asm volatile("ldmatrix.sync.aligned.m8n8.x4.shared.b16 {%0,%1,%2,%3}, [%4];"
                 : "=r"(r[0]), "=r"(r[1]), "=r"(r[2]), "=r"(r[3]) : "r"(addr));
}
__device__ __forceinline__ void ldm2(uint32_t* r, uint32_t addr) {
    asm volatile("ldmatrix.sync.aligned.m8n8.x2.shared.b16 {%0,%1}, [%2];"
                 : "=r"(r[0]), "=r"(r[1]) : "r"(addr));
}
__device__ __forceinline__ void mma_bf16(float* d, const uint32_t* a, const uint32_t* b) {
    asm volatile(
        "mma.sync.aligned.m16n8k16.row.col.f32.bf16.bf16.f32 "
        "{%0,%1,%2,%3}, {%4,%5,%6,%7}, {%8,%9}, {%0,%1,%2,%3};"
        : "+f"(d[0]), "+f"(d[1]), "+f"(d[2]), "+f"(d[3])
        : "r"(a[0]), "r"(a[1]), "r"(a[2]), "r"(a[3]), "r"(b[0]), "r"(b[1]));
}

// ======================= tensor-core GEMM (mma.sync, bf16 split) =========
// Cm[N x 128] (fp16) = A[N x K] (fp32) @ W[K x 128]; optional relu on A read.
// KC=16, 24.6KB smem, launch_bounds(256,2) -> 2 CTAs/SM (wave-quant fix).
__global__ __launch_bounds__(256, 2) void tc_gemm(const float* __restrict__ A,
                                                  const float* __restrict__ W,
                                                  __half* __restrict__ Cm,
                                                  int N, int K, int reluA) {
    __shared__ __align__(16) uint16_t Ah[128 * AST];
    __shared__ __align__(16) uint16_t Al[128 * AST];
    __shared__ __align__(16) uint16_t Bh[128 * AST];
    __shared__ __align__(16) uint16_t Bl[128 * AST];

    int tid = threadIdx.x;
    int lane = tid & 31;
    int wid = tid >> 5;
    int wm = wid & 1;
    int wn = wid >> 1;
    int row0 = blockIdx.x * 128;

    float acc[4][4][4];
#pragma unroll
    for (int i = 0; i < 4; i++)
#pragma unroll
        for (int j = 0; j < 4; j++)
#pragma unroll
            for (int q = 0; q < 4; q++) acc[i][j][q] = 0.f;

    uint32_t aBase = smem_u32(Ah);
    uint32_t alBase = smem_u32(Al);
    uint32_t bBase = smem_u32(Bh);
    uint32_t blBase = smem_u32(Bl);

    int aLRow = lane & 15;
    int aLK = (lane >> 4) * 8;
    int bLRow = lane & 7;
    int bLK = ((lane >> 3) & 1) * 8;

    for (int kb = 0; kb < K; kb += KC) {
        // ---- fill A: 128 rows x 16 k (4 float4 per row) ----
#pragma unroll
        for (int it = 0; it < 2; it++) {
            int idx = tid + it * 256;      // 0..511
            int row = idx >> 2;
            int f4 = idx & 3;
            float4 v = make_float4(0.f, 0.f, 0.f, 0.f);
            int gr = row0 + row;
            if (gr < N)
                v = *reinterpret_cast<const float4*>(A + (size_t)gr * K + kb + f4 * 4);
            if (reluA) {
                v.x = fmaxf(v.x, 0.f); v.y = fmaxf(v.y, 0.f);
                v.z = fmaxf(v.z, 0.f); v.w = fmaxf(v.w, 0.f);
            }
            uint32_t h01 = pack_bf(v.x, v.y);
            uint32_t h23 = pack_bf(v.z, v.w);
            uint32_t l01 = pack_bf(v.x - bflo_f(h01), v.y - bfhi_f(h01));
            uint32_t l23 = pack_bf(v.z - bflo_f(h23), v.w - bfhi_f(h23));
            int o = row * AST + f4 * 4;
            *reinterpret_cast<uint2*>(Ah + o) = make_uint2(h01, h23);
            *reinterpret_cast<uint2*>(Al + o) = make_uint2(l01, l23);
        }
        // ---- fill B: 128 n x 8 k-pairs ----
#pragma unroll
        for (int it = 0; it < 4; it++) {
            int idx = tid + it * 256;      // 0..1023
            int k2 = idx >> 7;             // 0..7
            int n = idx & 127;
            float v0 = W[(size_t)(kb + 2 * k2) * 128 + n];
            float v1 = W[(size_t)(kb + 2 * k2 + 1) * 128 + n];
            uint32_t h = pack_bf(v0, v1);
            uint32_t l = pack_bf(v0 - bflo_f(h), v1 - bfhi_f(h));
            int o = n * AST + k2 * 2;
            *reinterpret_cast<uint32_t*>(Bh + o) = h;
            *reinterpret_cast<uint32_t*>(Bl + o) = l;
        }
        __syncthreads();

        // ---- mma: single k16 step per chunk ----
        {
            uint32_t afh[4][4], afl[4][4];
#pragma unroll
            for (int mt = 0; mt < 4; mt++) {
                uint32_t off = (uint32_t)(((wm * 64 + mt * 16 + aLRow) * AST +
                                           aLK) * 2);
                ldm4(afh[mt], aBase + off);
                ldm4(afl[mt], alBase + off);
            }
            uint32_t bfh[4][2], bfl[4][2];
#pragma unroll
            for (int nt = 0; nt < 4; nt++) {
                uint32_t off = (uint32_t)(((wn * 32 + nt * 8 + bLRow) * AST +
                                           bLK) * 2);
                ldm2(bfh[nt], bBase + off);
                ldm2(bfl[nt], blBase + off);
            }
#pragma unroll
            for (int mt = 0; mt < 4; mt++)
#pragma unroll
                for (int nt = 0; nt < 4; nt++) {
                    mma_bf16(acc[mt][nt], afh[mt], bfh[nt]);
                    mma_bf16(acc[mt][nt], afh[mt], bfl[nt]);
                    mma_bf16(acc[mt][nt], afl[mt], bfh[nt]);
                }
        }
        __syncthreads();
    }

    int gid = lane >> 2;
    int tig = lane & 3;
#pragma unroll
    for (int mt = 0; mt < 4; mt++) {
        int r0 = row0 + wm * 64 + mt * 16 + gid;
        int r1 = r0 + 8;
#pragma unroll
        for (int nt = 0; nt < 4; nt++) {
            int col = wn * 32 + nt * 8 + tig * 2;
            if (r0 < N) {
                __half2 p = __floats2half2_rn(acc[mt][nt][0], acc[mt][nt][1]);
                *reinterpret_cast<__half2*>(Cm + (size_t)r0 * 128 + col) = p;
            }
            if (r1 < N) {
                __half2 p = __floats2half2_rn(acc[mt][nt][2], acc[mt][nt][3]);
                *reinterpret_cast<__half2*>(Cm + (size_t)r1 * 128 + col) = p;
            }
        }
    }
}

// ---------------- precompute ---------------------------------------------
__global__ void init_deg_kernel(int n) {
    int i = blockIdx.x * blockDim.x + threadIdx.x;
    if (i < n) { g_deg[i] = 1.0f; g_cnt[i] = 0; }
}

__global__ void accum_deg_kernel(const int* __restrict__ dst,
                                 const float* __restrict__ ew, int E) {
    int e = blockIdx.x * blockDim.x + threadIdx.x;
    if (e < E) {
        int d = dst[e];
        atomicAdd(&g_deg[d], ew[e]);
        atomicAdd(&g_cnt[d], 1);
    }
}

// scan phase1 with dinv fused (both depend only on accum_deg)
__global__ __launch_bounds__(SCANB) void scan_phase1(int n) {
    __shared__ int warpsum[32];
    int tid = threadIdx.x, lane = tid & 31, wid = tid >> 5;
    int i = blockIdx.x * SCANB + tid;

    if (i < n) {
        float d = g_deg[i];
        float r = (d > 0.0f) ? rsqrtf(d) : 0.0f;
        g_dinv[i] = r;
        g_selfc[i] = r * r;
    }

    int v = (i < n) ? g_cnt[i] : 0;
    int x = v;
#pragma unroll
    for (int off = 1; off < 32; off <<= 1) {
        int y = __shfl_up_sync(0xffffffffu, x, off);
        if (lane >= off) x += y;
    }
    if (lane == 31) warpsum[wid] = x;
    __syncthreads();
    if (wid == 0) {
        int s = warpsum[lane];
#pragma unroll
        for (int off = 1; off < 32; off <<= 1) {
            int y = __shfl_up_sync(0xffffffffu, s, off);
            if (lane >= off) s += y;
        }
        warpsum[lane] = s;
    }
    __syncthreads();
    int woff = wid ? warpsum[wid - 1] : 0;
    if (i < n) g_rowoff[i] = x + woff - v;
    if (tid == SCANB - 1) g_bsum[blockIdx.x] = x + woff;
}

// scan phase2+3 merged
__global__ void scan_phase23(int nb, int n) {
    __shared__ int boff_s[64];
    __shared__ int ws2[2];
    int tid = threadIdx.x;
    int lane = tid & 31;
    int w = tid >> 5;

    int v = 0, x = 0;
    if (tid < 64) {
        v = (tid < nb) ? g_bsum[tid] : 0;
        x = v;
#pragma unroll
        for (int off = 1; off < 32; off <<= 1) {
            int y = __shfl_up_sync(0xffffffffu, x, off);
            if (lane >= off) x += y;
        }
        if (lane == 31) ws2[w] = x;
    }
    __syncthreads();
    if (tid < 64) {
        int add = (w == 1) ? ws2[0] : 0;
        boff_s[tid] = x + add - v;
        if (blockIdx.x == 0 && tid == nb - 1) g_rowoff[n] = x + add;
    }
    __syncthreads();

    int i = blockIdx.x * blockDim.x + tid;
    if (i < n) {
        int r = g_rowoff[i] + boff_s[i / SCANB];
        g_rowoff[i] = r;
        g_pos[i] = r;
    }
}

__global__ void fill_kernel(const int* __restrict__ src, const int* __restrict__ dst,
                            const float* __restrict__ ew, int E) {
    int e = blockIdx.x * blockDim.x + threadIdx.x;
    if (e < E) {
        int s = src[e], d = dst[e];
        int slot = atomicAdd(&g_pos[d], 1);
        g_csr_src[slot] = s;
        g_csr_coef[slot] = g_dinv[s] * ew[e] * g_dinv[d];
    }
}

// ---------------- CSR gather aggregation (warp per node, fp16 h) ---------
__global__ void gather_kernel(const float* __restrict__ b, int n) {
    int t = blockIdx.x * blockDim.x + threadIdx.x;
    int node = t >> 5;
    int lane = t & 31;
    if (node >= n) return;

    const __half2* h2 = reinterpret_cast<const __half2*>(g_h);
    float4 bv = reinterpret_cast<const float4*>(b)[lane];
    float sc = g_selfc[node];

    float4 acc;
    {
        __half2 a0 = h2[(size_t)node * 64 + 2 * lane];
        __half2 a1 = h2[(size_t)node * 64 + 2 * lane + 1];
        float2 f0 = __half22float2(a0);
        float2 f1 = __half22float2(a1);
        acc.x = fmaf(f0.x, sc, bv.x);
        acc.y = fmaf(f0.y, sc, bv.y);
        acc.z = fmaf(f1.x, sc, bv.z);
        acc.w = fmaf(f1.y, sc, bv.w);
    }

    int beg = g_rowoff[node];
    int end = g_rowoff[node + 1];
    int e = beg;
    for (; e + 3 < end; e += 4) {
        int s0 = __ldg(g_csr_src + e);
        int s1 = __ldg(g_csr_src + e + 1);
        int s2 = __ldg(g_csr_src + e + 2);
        int s3 = __ldg(g_csr_src + e + 3);
        float w0 = __ldg(g_csr_coef + e);
        float w1 = __ldg(g_csr_coef + e + 1);
        float w2 = __ldg(g_csr_coef + e + 2);
        float w3 = __ldg(g_csr_coef + e + 3);
        __half2 a0 = h2[(size_t)s0 * 64 + 2 * lane];
        __half2 a1 = h2[(size_t)s0 * 64 + 2 * lane + 1];
        __half2 c0 = h2[(size_t)s1 * 64 + 2 * lane];
        __half2 c1 = h2[(size_t)s1 * 64 + 2 * lane + 1];
        __half2 d0 = h2[(size_t)s2 * 64 + 2 * lane];
        __half2 d1 = h2[(size_t)s2 * 64 + 2 * lane + 1];
        __half2 e0 = h2[(size_t)s3 * 64 + 2 * lane];
        __half2 e1 = h2[(size_t)s3 * 64 + 2 * lane + 1];
        float2 f0 = __half22float2(a0);
        float2 f1 = __half22float2(a1);
        float2 g0 = __half22float2(c0);
        float2 g1 = __half22float2(c1);
        float2 h0 = __half22float2(d0);
        float2 h1 = __half22float2(d1);
        float2 i0 = __half22float2(e0);
        float2 i1 = __half22float2(e1);
        acc.x = fmaf(f0.x, w0, acc.x);
        acc.y = fmaf(f0.y, w0, acc.y);
        acc.z = fmaf(f1.x, w0, acc.z);
        acc.w = fmaf(f1.y, w0, acc.w);
        acc.x = fmaf(g0.x, w1, acc.x);
        acc.y = fmaf(g0.y, w1, acc.y);
        acc.z = fmaf(g1.x, w1, acc.z);
        acc.w = fmaf(g1.y, w1, acc.w);
        acc.x = fmaf(h0.x, w2, acc.x);
        acc.y = fmaf(h0.y, w2, acc.y);
        acc.z = fmaf(h1.x, w2, acc.z);
        acc.w = fmaf(h1.y, w2, acc.w);
        acc.x = fmaf(i0.x, w3, acc.x);
        acc.y = fmaf(i0.y, w3, acc.y);
        acc.z = fmaf(i1.x, w3, acc.z);
        acc.w = fmaf(i1.y, w3, acc.w);
    }
    for (; e < end; e++) {
        int s0 = __ldg(g_csr_src + e);
        float w0 = __ldg(g_csr_coef + e);
        __half2 a0 = h2[(size_t)s0 * 64 + 2 * lane];
        __half2 a1 = h2[(size_t)s0 * 64 + 2 * lane + 1];
        float2 f0 = __half22float2(a0);
        float2 f1 = __half22float2(a1);
        acc.x = fmaf(f0.x, w0, acc.x);
        acc.y = fmaf(f0.y, w0, acc.y);
        acc.z = fmaf(f1.x, w0, acc.z);
        acc.w = fmaf(f1.y, w0, acc.w);
    }
    reinterpret_cast<float4*>(g_agg)[(size_t)node * 32 + lane] = acc;
}

// ---------------- FC + softmax (warp per node) ---------------------------
__global__ void fc_softmax_kernel(const float* __restrict__ fw,
                                  const float* __restrict__ fb,
                                  float* __restrict__ out, int n) {
    int warp = (blockIdx.x * blockDim.x + threadIdx.x) >> 5;
    int lane = threadIdx.x & 31;
    if (warp >= n) return;
    const float* hr = g_agg + (size_t)warp * NH;

    float acc[NC];
#pragma unroll
    for (int c = 0; c < NC; c++) acc[c] = 0.0f;
#pragma unroll
    for (int kk = 0; kk < 4; kk++) {
        int k = lane + kk * 32;
        float hv = fmaxf(hr[k], 0.0f);
#pragma unroll
        for (int c = 0; c < NC; c++) acc[c] = fmaf(hv, __ldg(fw + k * NC + c), acc[c]);
    }
#pragma unroll
    for (int c = 0; c < NC; c++) {
#pragma unroll
        for (int off = 16; off; off >>= 1)
            acc[c] += __shfl_xor_sync(0xffffffffu, acc[c], off);
        acc[c] += fb[c];
    }
    float mx = acc[0];
#pragma unroll
    for (int c = 1; c < NC; c++) mx = fmaxf(mx, acc[c]);
    float ex[NC];
    float sum = 0.0f;
#pragma unroll
    for (int c = 0; c < NC; c++) { ex[c] = __expf(acc[c] - mx); sum += ex[c]; }
    float inv = 1.0f / sum;
    if (lane < NC) out[(size_t)warp * NC + lane] = ex[lane] * inv;
}

// ---------------- launch -------------------------------------------------
extern "C" void kernel_launch(void* const* d_in, const int* in_sizes, int n_in,
                              void* d_out, int out_size) {
    const float* x  = (const float*)d_in[0];
    const int*   ei = (const int*)d_in[1];
    const float* ew = (const float*)d_in[2];
    const float* W1 = (const float*)d_in[3];
    const float* b1 = (const float*)d_in[4];
    const float* W2 = (const float*)d_in[5];
    const float* b2 = (const float*)d_in[6];
    const float* W3 = (const float*)d_in[7];
    const float* b3 = (const float*)d_in[8];
    const float* fw = (const float*)d_in[9];
    const float* fb = (const float*)d_in[10];
    float* out = (float*)d_out;

    int N = in_sizes[0] / NF;
    int E = in_sizes[2];
    const int* src = ei;
    const int* dst = ei + E;

    __half* hbuf;
    float* aggbuf;
    cudaGetSymbolAddress((void**)&hbuf, g_h);
    cudaGetSymbolAddress((void**)&aggbuf, g_agg);

    const int T = 256;
    int gN = (N + T - 1) / T;
    int gE = (E + T - 1) / T;
    int gGa = (N * 32 + T - 1) / T;
    int gG = (N + 127) / 128;
    int nb = (N + SCANB - 1) / SCANB;

    init_deg_kernel<<<gN, T>>>(N);
    accum_deg_kernel<<<gE, T>>>(dst, ew, E);
    scan_phase1<<<nb, SCANB>>>(N);
    scan_phase23<<<gN, T>>>(nb, N);
    fill_kernel<<<gE, T>>>(src, dst, ew, E);

    tc_gemm<<<gG, T>>>(x, W1, hbuf, N, NF, 0);
    gather_kernel<<<gGa, T>>>(b1, N);
    tc_gemm<<<gG, T>>>(aggbuf, W2, hbuf, N, NH, 1);
    gather_kernel<<<gGa, T>>>(b2, N);
    tc_gemm<<<gG, T>>>(aggbuf, W3, hbuf, N, NH, 1);
    gather_kernel<<<gGa, T>>>(b3, N);
    fc_softmax_kernel<<<gGa, T>>>(fw, fb, out, N);
}